// round 5
// baseline (speedup 1.0000x reference)
#include <cuda_runtime.h>
#include <cuda_bf16.h>
#include <cstdint>

#define SEQ 2048
#define DIM 64
#define NBH 32   // B*H

// Scratch (no allocs allowed)
__device__ __nv_bfloat16 g_vt_hi[(size_t)NBH * DIM * SEQ];
__device__ __nv_bfloat16 g_vt_lo[(size_t)NBH * DIM * SEQ];
__device__ float    g_psum[(size_t)NBH * 16 * SEQ];   // [bh][ntile][row]
__device__ float    g_inv[(size_t)NBH * SEQ];         // [bh][row]
__device__ uint32_t g_mbits[(size_t)SEQ * (SEQ / 32)];// [row][word]

// ---------------- helpers ----------------
__device__ __forceinline__ uint32_t smem_u32(const void* p) {
    uint32_t a;
    asm("{ .reg .u64 t; cvta.to.shared.u64 t, %1; cvt.u32.u64 %0, t; }" : "=r"(a) : "l"(p));
    return a;
}
__device__ __forceinline__ void ldsm_x4(uint32_t r[4], uint32_t addr) {
    asm volatile("ldmatrix.sync.aligned.m8n8.x4.shared.b16 {%0,%1,%2,%3}, [%4];"
        : "=r"(r[0]), "=r"(r[1]), "=r"(r[2]), "=r"(r[3]) : "r"(addr));
}
__device__ __forceinline__ void ldsm_x2(uint32_t r[2], uint32_t addr) {
    asm volatile("ldmatrix.sync.aligned.m8n8.x2.shared.b16 {%0,%1}, [%2];"
        : "=r"(r[0]), "=r"(r[1]) : "r"(addr));
}
__device__ __forceinline__ void mma16816(float c[4], const uint32_t a[4], const uint32_t b[2]) {
    asm volatile(
        "mma.sync.aligned.m16n8k16.row.col.f32.bf16.bf16.f32 "
        "{%0,%1,%2,%3}, {%4,%5,%6,%7}, {%8,%9}, {%0,%1,%2,%3};"
        : "+f"(c[0]), "+f"(c[1]), "+f"(c[2]), "+f"(c[3])
        : "r"(a[0]), "r"(a[1]), "r"(a[2]), "r"(a[3]), "r"(b[0]), "r"(b[1]));
}
__device__ __forceinline__ void split4(float4 v, uint32_t& h01, uint32_t& h23,
                                       uint32_t& l01, uint32_t& l23) {
    __nv_bfloat16 h0 = __float2bfloat16_rn(v.x);
    __nv_bfloat16 h1 = __float2bfloat16_rn(v.y);
    __nv_bfloat16 h2 = __float2bfloat16_rn(v.z);
    __nv_bfloat16 h3 = __float2bfloat16_rn(v.w);
    __nv_bfloat16 q0 = __float2bfloat16_rn(v.x - __bfloat162float(h0));
    __nv_bfloat16 q1 = __float2bfloat16_rn(v.y - __bfloat162float(h1));
    __nv_bfloat16 q2 = __float2bfloat16_rn(v.z - __bfloat162float(h2));
    __nv_bfloat16 q3 = __float2bfloat16_rn(v.w - __bfloat162float(h3));
    h01 = (uint32_t)__bfloat16_as_ushort(h0) | ((uint32_t)__bfloat16_as_ushort(h1) << 16);
    h23 = (uint32_t)__bfloat16_as_ushort(h2) | ((uint32_t)__bfloat16_as_ushort(h3) << 16);
    l01 = (uint32_t)__bfloat16_as_ushort(q0) | ((uint32_t)__bfloat16_as_ushort(q1) << 16);
    l23 = (uint32_t)__bfloat16_as_ushort(q2) | ((uint32_t)__bfloat16_as_ushort(q3) << 16);
}
#define RS 72   // smem row stride in bf16 (144B, conflict-free ldmatrix)

// ---------------- Kernel A: mask -> bitmask ----------------
__global__ __launch_bounds__(256) void mask_compress(const int* __restrict__ mask) {
    int w = blockIdx.x * 256 + threadIdx.x;            // word index, 131072 total
    const int4* m4 = (const int4*)mask + (size_t)w * 8;
    uint32_t b = 0;
    #pragma unroll
    for (int i = 0; i < 8; i++) {
        int4 v = m4[i];
        b |= (uint32_t)(v.x != 0) << (i * 4 + 0);
        b |= (uint32_t)(v.y != 0) << (i * 4 + 1);
        b |= (uint32_t)(v.z != 0) << (i * 4 + 2);
        b |= (uint32_t)(v.w != 0) << (i * 4 + 3);
    }
    g_mbits[w] = b;
}

// ---------------- Kernel B: V -> Vt (bf16 hi/lo, [bh][n][k]) ----------------
__global__ __launch_bounds__(256) void vt_prep(const float* __restrict__ V) {
    __shared__ float tile[128][DIM + 1];
    const int bh = blockIdx.y;
    const int k0 = blockIdx.x * 128;
    const int tid = threadIdx.x;

    const float4* V4 = (const float4*)(V + ((size_t)bh * SEQ + k0) * DIM);
    #pragma unroll
    for (int p = 0; p < 8; p++) {
        int lin = tid + p * 256;
        int r = lin >> 4, j = lin & 15;
        float4 v = V4[lin];
        tile[r][j * 4 + 0] = v.x; tile[r][j * 4 + 1] = v.y;
        tile[r][j * 4 + 2] = v.z; tile[r][j * 4 + 3] = v.w;
    }
    __syncthreads();
    #pragma unroll
    for (int p = 0; p < 32; p++) {
        int lin = tid + p * 256;
        int n = lin >> 7, k = lin & 127;
        float x = tile[k][n];
        __nv_bfloat16 h = __float2bfloat16_rn(x);
        __nv_bfloat16 l = __float2bfloat16_rn(x - __bfloat162float(h));
        size_t o = ((size_t)bh * DIM + n) * SEQ + k0 + k;
        g_vt_hi[o] = h;
        g_vt_lo[o] = l;
    }
}

// ---------------- Kernel C: p = exp(mask ? QK^T/8 : -inf), partial row sums -
__global__ __launch_bounds__(256) void qk_exp(const float* __restrict__ Q,
                                              const float* __restrict__ K,
                                              float* __restrict__ pbuf) {
    extern __shared__ char sm[];
    __shared__ float spsum[128];
    constexpr int QHI = 0, QLO = 18432, KHI = 36864, KLO = 55296;
    const uint32_t sb = smem_u32(sm);
    const int tid = threadIdx.x, wid = tid >> 5, l = tid & 31;
    const int bh = blockIdx.z, m0 = blockIdx.y * 128, n0 = blockIdx.x * 128;
    const int nx = blockIdx.x;

    if (tid < 128) spsum[tid] = 0.f;

    const float4* Qg = (const float4*)(Q + ((size_t)bh * SEQ + m0) * DIM);
    const float4* Kg = (const float4*)(K + ((size_t)bh * SEQ + n0) * DIM);
    #pragma unroll
    for (int p = 0; p < 8; p++) {
        int lin = tid + p * 256;
        int r = lin >> 4, j = lin & 15;
        uint32_t off = (uint32_t)(r * RS + j * 4) * 2;
        uint32_t h01, h23, l01, l23;
        split4(Qg[lin], h01, h23, l01, l23);
        *(uint2*)(sm + QHI + off) = make_uint2(h01, h23);
        *(uint2*)(sm + QLO + off) = make_uint2(l01, l23);
        split4(Kg[lin], h01, h23, l01, l23);
        *(uint2*)(sm + KHI + off) = make_uint2(h01, h23);
        *(uint2*)(sm + KLO + off) = make_uint2(l01, l23);
    }
    __syncthreads();

    const int wm = wid >> 2, wn = wid & 3;
    const int mbase = wm * 64, nbase = wn * 32;
    const int lr = l & 7, sub = l >> 3;

    float acc[4][4][4];
    #pragma unroll
    for (int a = 0; a < 4; a++)
        #pragma unroll
        for (int b = 0; b < 4; b++)
            #pragma unroll
            for (int c = 0; c < 4; c++) acc[a][b][c] = 0.f;

    const int arow_lane = lr + (sub & 1) * 8;
    const uint32_t akc_lane = (uint32_t)((sub >> 1) * 8);
    const uint32_t bkc_lane = (uint32_t)((sub & 1) * 8);

    #pragma unroll
    for (int ks = 0; ks < 4; ks++) {
        uint32_t ah[4][4], al[4][4];
        #pragma unroll
        for (int mt = 0; mt < 4; mt++) {
            int row = mbase + mt * 16 + arow_lane;
            uint32_t off = (uint32_t)(row * RS) * 2 + (akc_lane + ks * 16) * 2;
            ldsm_x4(ah[mt], sb + QHI + off);
            ldsm_x4(al[mt], sb + QLO + off);
        }
        #pragma unroll
        for (int nt = 0; nt < 4; nt++) {
            int rowN = nbase + nt * 8 + lr;
            uint32_t off = (uint32_t)(rowN * RS) * 2 + (bkc_lane + ks * 16) * 2;
            uint32_t bhf[2], blf[2];
            ldsm_x2(bhf, sb + KHI + off);
            ldsm_x2(blf, sb + KLO + off);
            #pragma unroll
            for (int mt = 0; mt < 4; mt++) {
                mma16816(acc[mt][nt], ah[mt], bhf);
                mma16816(acc[mt][nt], ah[mt], blf);
                mma16816(acc[mt][nt], al[mt], bhf);
            }
        }
    }

    // epilogue: mask -> exp -> store p, accumulate row sums
    const int g = l >> 2, q2 = (l & 3) * 2;
    const int mword = (n0 + nbase) >> 5;
    float* so = pbuf + (size_t)bh * SEQ * SEQ;

    #pragma unroll
    for (int mt = 0; mt < 4; mt++) {
        int row = m0 + mbase + mt * 16 + g;
        uint32_t w0 = g_mbits[(size_t)row * 64 + mword];
        uint32_t w1 = g_mbits[(size_t)(row + 8) * 64 + mword];
        float s0 = 0.f, s1 = 0.f;
        #pragma unroll
        for (int nt = 0; nt < 4; nt++) {
            int cb = nt * 8 + q2;
            float e0 = ((w0 >> cb) & 1)       ? __expf(acc[mt][nt][0] * 0.125f) : 0.f;
            float e1 = ((w0 >> (cb + 1)) & 1) ? __expf(acc[mt][nt][1] * 0.125f) : 0.f;
            float e2 = ((w1 >> cb) & 1)       ? __expf(acc[mt][nt][2] * 0.125f) : 0.f;
            float e3 = ((w1 >> (cb + 1)) & 1) ? __expf(acc[mt][nt][3] * 0.125f) : 0.f;
            int col = n0 + nbase + cb;
            *(float2*)&so[(size_t)row * SEQ + col] = make_float2(e0, e1);
            *(float2*)&so[(size_t)(row + 8) * SEQ + col] = make_float2(e2, e3);
            s0 += e0 + e1;
            s1 += e2 + e3;
        }
        // reduce across the 4 lanes of this quad (same row)
        s0 += __shfl_xor_sync(0xffffffffu, s0, 1);
        s0 += __shfl_xor_sync(0xffffffffu, s0, 2);
        s1 += __shfl_xor_sync(0xffffffffu, s1, 1);
        s1 += __shfl_xor_sync(0xffffffffu, s1, 2);
        if ((l & 3) == 0) {
            atomicAdd(&spsum[mbase + mt * 16 + g], s0);
            atomicAdd(&spsum[mbase + mt * 16 + g + 8], s1);
        }
    }
    __syncthreads();
    if (tid < 128)
        g_psum[((size_t)bh * 16 + nx) * SEQ + m0 + tid] = spsum[tid];
}

// ---------------- Kernel D: inv row sums ----------------
__global__ __launch_bounds__(256) void reduce_inv() {
    int idx = blockIdx.x * 256 + threadIdx.x;   // bh*SEQ + row
    int bh = idx >> 11, row = idx & 2047;
    float s = 0.f;
    #pragma unroll
    for (int nx = 0; nx < 16; nx++)
        s += g_psum[((size_t)bh * 16 + nx) * SEQ + row];
    g_inv[idx] = 1.0f / s;
}

// ---------------- Kernel E: normalize + write attn + out = attn @ V ---------
__global__ __launch_bounds__(256) void attnv_norm(float* __restrict__ attn,
                                                  float* __restrict__ out) {
    extern __shared__ char sm[];
    __shared__ float sinv[128];
    constexpr int AHI = 0, ALO = 18432, BHI = 36864, BLO = 46080;
    const uint32_t sb = smem_u32(sm);
    const int tid = threadIdx.x, wid = tid >> 5, l = tid & 31;
    const int bh = blockIdx.y, m0 = blockIdx.x * 128;

    if (tid < 128) sinv[tid] = g_inv[(size_t)bh * SEQ + m0 + tid];
    __syncthreads();

    const int wm = wid >> 1, wn = wid & 1;
    const int mbase = wm * 32, nbase = wn * 32;
    const int lr = l & 7, sub = l >> 3;
    const int arow_lane = lr + (sub & 1) * 8;
    const uint32_t akc_lane = (uint32_t)((sub >> 1) * 8);
    const uint32_t bkc_lane = (uint32_t)((sub & 1) * 8);

    float4* Ag = (float4*)(attn + ((size_t)bh * SEQ + m0) * SEQ);
    const __nv_bfloat16* vh = g_vt_hi + (size_t)bh * DIM * SEQ;
    const __nv_bfloat16* vl = g_vt_lo + (size_t)bh * DIM * SEQ;

    float acc[2][4][4];
    #pragma unroll
    for (int a = 0; a < 2; a++)
        #pragma unroll
        for (int b = 0; b < 4; b++)
            #pragma unroll
            for (int c = 0; c < 4; c++) acc[a][b][c] = 0.f;

    for (int kt = 0; kt < SEQ / 64; kt++) {
        // A chunk: read p, normalize, write back attn, convert bf16 hi/lo
        #pragma unroll
        for (int p = 0; p < 8; p++) {
            int lin = tid + p * 256;
            int r = lin >> 4, j = lin & 15;
            size_t gi = (size_t)r * (SEQ / 4) + kt * 16 + j;
            float4 v = Ag[gi];
            float iv = sinv[r];
            float4 a = make_float4(v.x * iv, v.y * iv, v.z * iv, v.w * iv);
            Ag[gi] = a;
            uint32_t h01, h23, l01, l23;
            split4(a, h01, h23, l01, l23);
            uint32_t off = (uint32_t)(r * RS + j * 4) * 2;
            *(uint2*)(sm + AHI + off) = make_uint2(h01, h23);
            *(uint2*)(sm + ALO + off) = make_uint2(l01, l23);
        }
        // B chunk: Vt[0..63][kt*64..+63] bf16 (pre-split)
        #pragma unroll
        for (int p = 0; p < 2; p++) {
            int lin = tid + p * 256;
            int n = lin >> 3, jj = lin & 7;
            size_t go = (size_t)n * SEQ + kt * 64 + jj * 8;
            uint32_t off = (uint32_t)(n * RS + jj * 8) * 2;
            *(uint4*)(sm + BHI + off) = *(const uint4*)(vh + go);
            *(uint4*)(sm + BLO + off) = *(const uint4*)(vl + go);
        }
        __syncthreads();

        #pragma unroll
        for (int ks = 0; ks < 4; ks++) {
            uint32_t ah[2][4], al[2][4];
            #pragma unroll
            for (int mt = 0; mt < 2; mt++) {
                int row = mbase + mt * 16 + arow_lane;
                uint32_t off = (uint32_t)(row * RS) * 2 + (akc_lane + ks * 16) * 2;
                ldsm_x4(ah[mt], sb + AHI + off);
                ldsm_x4(al[mt], sb + ALO + off);
            }
            #pragma unroll
            for (int nt = 0; nt < 4; nt++) {
                int rowN = nbase + nt * 8 + lr;
                uint32_t off = (uint32_t)(rowN * RS) * 2 + (bkc_lane + ks * 16) * 2;
                uint32_t bhf[2], blf[2];
                ldsm_x2(bhf, sb + BHI + off);
                ldsm_x2(blf, sb + BLO + off);
                #pragma unroll
                for (int mt = 0; mt < 2; mt++) {
                    mma16816(acc[mt][nt], ah[mt], bhf);
                    mma16816(acc[mt][nt], ah[mt], blf);
                    mma16816(acc[mt][nt], al[mt], bhf);
                }
            }
        }
        __syncthreads();
    }

    const int g = l >> 2, q2 = (l & 3) * 2;
    float* ob = out + ((size_t)bh * SEQ + m0) * DIM;
    #pragma unroll
    for (int mt = 0; mt < 2; mt++) {
        #pragma unroll
        for (int nt = 0; nt < 4; nt++) {
            int row = mbase + mt * 16 + g;
            int col = nbase + nt * 8 + q2;
            *(float2*)&ob[(size_t)row * DIM + col] = make_float2(acc[mt][nt][0], acc[mt][nt][1]);
            *(float2*)&ob[(size_t)(row + 8) * DIM + col] = make_float2(acc[mt][nt][2], acc[mt][nt][3]);
        }
    }
}

// ---------------- launch ----------------
extern "C" void kernel_launch(void* const* d_in, const int* in_sizes, int n_in,
                              void* d_out, int out_size) {
    const float* Q    = (const float*)d_in[0];
    const float* K    = (const float*)d_in[1];
    const float* V    = (const float*)d_in[2];
    const int*   mask = (const int*)d_in[3];

    float* out  = (float*)d_out;                      // [B,H,S,D]
    float* attn = out + (size_t)NBH * SEQ * DIM;      // [B,H,S,S]

    constexpr int QK_SMEM = 4 * 128 * RS * 2;                    // 73728
    constexpr int AV_SMEM = 2 * 128 * RS * 2 + 2 * 64 * RS * 2;  // 55296
    cudaFuncSetAttribute(qk_exp, cudaFuncAttributeMaxDynamicSharedMemorySize, QK_SMEM);
    cudaFuncSetAttribute(attnv_norm, cudaFuncAttributeMaxDynamicSharedMemorySize, AV_SMEM);

    mask_compress<<<SEQ * (SEQ / 32) / 256, 256>>>(mask);

    dim3 g0(SEQ / 128, NBH);
    vt_prep<<<g0, 256>>>(V);

    dim3 g1(SEQ / 128, SEQ / 128, NBH);
    qk_exp<<<g1, 256, QK_SMEM>>>(Q, K, attn);

    reduce_inv<<<NBH * SEQ / 256, 256>>>();

    dim3 g3(SEQ / 128, NBH);
    attnv_norm<<<g3, 256, AV_SMEM>>>(attn, out);
}

// round 6
// speedup vs baseline: 1.2988x; 1.2988x over previous
#include <cuda_runtime.h>
#include <cuda_bf16.h>
#include <cstdint>

#define SEQ 2048
#define DIM 64
#define NBH 32   // B*H

// Scratch (device globals; no allocs allowed)
__device__ __nv_bfloat16 g_qh[(size_t)NBH * SEQ * DIM];
__device__ __nv_bfloat16 g_ql[(size_t)NBH * SEQ * DIM];
__device__ __nv_bfloat16 g_kh[(size_t)NBH * SEQ * DIM];
__device__ __nv_bfloat16 g_kl[(size_t)NBH * SEQ * DIM];
__device__ __nv_bfloat16 g_vt_hi[(size_t)NBH * DIM * SEQ];
__device__ __nv_bfloat16 g_vt_lo[(size_t)NBH * DIM * SEQ];
__device__ __nv_bfloat16 g_ah[(size_t)NBH * SEQ * SEQ];
__device__ __nv_bfloat16 g_al[(size_t)NBH * SEQ * SEQ];

// ---------------- helpers ----------------
__device__ __forceinline__ uint32_t smem_u32(const void* p) {
    uint32_t a;
    asm("{ .reg .u64 t; cvta.to.shared.u64 t, %1; cvt.u32.u64 %0, t; }" : "=r"(a) : "l"(p));
    return a;
}
__device__ __forceinline__ void ldsm_x4(uint32_t r[4], uint32_t addr) {
    asm volatile("ldmatrix.sync.aligned.m8n8.x4.shared.b16 {%0,%1,%2,%3}, [%4];"
        : "=r"(r[0]), "=r"(r[1]), "=r"(r[2]), "=r"(r[3]) : "r"(addr));
}
__device__ __forceinline__ void ldsm_x2(uint32_t r[2], uint32_t addr) {
    asm volatile("ldmatrix.sync.aligned.m8n8.x2.shared.b16 {%0,%1}, [%2];"
        : "=r"(r[0]), "=r"(r[1]) : "r"(addr));
}
__device__ __forceinline__ void mma16816(float c[4], const uint32_t a[4], const uint32_t b[2]) {
    asm volatile(
        "mma.sync.aligned.m16n8k16.row.col.f32.bf16.bf16.f32 "
        "{%0,%1,%2,%3}, {%4,%5,%6,%7}, {%8,%9}, {%0,%1,%2,%3};"
        : "+f"(c[0]), "+f"(c[1]), "+f"(c[2]), "+f"(c[3])
        : "r"(a[0]), "r"(a[1]), "r"(a[2]), "r"(a[3]), "r"(b[0]), "r"(b[1]));
}
__device__ __forceinline__ void split4(float4 v, uint32_t& h01, uint32_t& h23,
                                       uint32_t& l01, uint32_t& l23) {
    __nv_bfloat16 h0 = __float2bfloat16_rn(v.x);
    __nv_bfloat16 h1 = __float2bfloat16_rn(v.y);
    __nv_bfloat16 h2 = __float2bfloat16_rn(v.z);
    __nv_bfloat16 h3 = __float2bfloat16_rn(v.w);
    __nv_bfloat16 q0 = __float2bfloat16_rn(v.x - __bfloat162float(h0));
    __nv_bfloat16 q1 = __float2bfloat16_rn(v.y - __bfloat162float(h1));
    __nv_bfloat16 q2 = __float2bfloat16_rn(v.z - __bfloat162float(h2));
    __nv_bfloat16 q3 = __float2bfloat16_rn(v.w - __bfloat162float(h3));
    h01 = (uint32_t)__bfloat16_as_ushort(h0) | ((uint32_t)__bfloat16_as_ushort(h1) << 16);
    h23 = (uint32_t)__bfloat16_as_ushort(h2) | ((uint32_t)__bfloat16_as_ushort(h3) << 16);
    l01 = (uint32_t)__bfloat16_as_ushort(q0) | ((uint32_t)__bfloat16_as_ushort(q1) << 16);
    l23 = (uint32_t)__bfloat16_as_ushort(q2) | ((uint32_t)__bfloat16_as_ushort(q3) << 16);
}
#define RS 72   // smem row stride in bf16 (144B, conflict-free ldmatrix)

// ---------------- Kernel A: elementwise fp32 -> bf16 hi/lo (optional scale) -
__global__ __launch_bounds__(256) void split_prep(const float* __restrict__ X,
                                                  __nv_bfloat16* __restrict__ hi,
                                                  __nv_bfloat16* __restrict__ lo,
                                                  float scale) {
    size_t i = (size_t)blockIdx.x * 256 + threadIdx.x;
    float4 v = ((const float4*)X)[i];
    v.x *= scale; v.y *= scale; v.z *= scale; v.w *= scale;
    uint32_t h01, h23, l01, l23;
    split4(v, h01, h23, l01, l23);
    ((uint2*)hi)[i] = make_uint2(h01, h23);
    ((uint2*)lo)[i] = make_uint2(l01, l23);
}

// ---------------- Kernel B: V -> Vt (bf16 hi/lo, [bh][n][k]) ----------------
__global__ __launch_bounds__(256) void vt_prep(const float* __restrict__ V) {
    __shared__ float tile[128][DIM + 1];
    const int bh = blockIdx.y;
    const int k0 = blockIdx.x * 128;
    const int tid = threadIdx.x;

    const float4* V4 = (const float4*)(V + ((size_t)bh * SEQ + k0) * DIM);
    #pragma unroll
    for (int p = 0; p < 8; p++) {
        int lin = tid + p * 256;
        int r = lin >> 4, j = lin & 15;
        float4 v = V4[lin];
        tile[r][j * 4 + 0] = v.x; tile[r][j * 4 + 1] = v.y;
        tile[r][j * 4 + 2] = v.z; tile[r][j * 4 + 3] = v.w;
    }
    __syncthreads();
    #pragma unroll
    for (int p = 0; p < 32; p++) {
        int lin = tid + p * 256;
        int n = lin >> 7, k = lin & 127;
        float x = tile[k][n];
        __nv_bfloat16 h = __float2bfloat16_rn(x);
        __nv_bfloat16 l = __float2bfloat16_rn(x - __bfloat162float(h));
        size_t o = ((size_t)bh * DIM + n) * SEQ + k0 + k;
        g_vt_hi[o] = h;
        g_vt_lo[o] = l;
    }
}

// ---------------- Kernel C: scores = (Q/8) K^T (HMMA, pre-split bf16) -------
__global__ __launch_bounds__(256) void qk_mma(float* __restrict__ scores) {
    extern __shared__ char sm[];
    constexpr int QHI = 0, QLO = 18432, KHI = 36864, KLO = 55296;
    const uint32_t sb = smem_u32(sm);
    const int tid = threadIdx.x, wid = tid >> 5, l = tid & 31;
    const int bh = blockIdx.z, m0 = blockIdx.y * 128, n0 = blockIdx.x * 128;

    const uint4* Qh4 = (const uint4*)(g_qh + ((size_t)bh * SEQ + m0) * DIM);
    const uint4* Ql4 = (const uint4*)(g_ql + ((size_t)bh * SEQ + m0) * DIM);
    const uint4* Kh4 = (const uint4*)(g_kh + ((size_t)bh * SEQ + n0) * DIM);
    const uint4* Kl4 = (const uint4*)(g_kl + ((size_t)bh * SEQ + n0) * DIM);
    #pragma unroll
    for (int p = 0; p < 4; p++) {
        int lin = tid + p * 256;           // 0..1023 (128 rows x 8 uint4)
        int r = lin >> 3, c = lin & 7;
        uint32_t off = (uint32_t)(r * RS + c * 8) * 2;
        *(uint4*)(sm + QHI + off) = Qh4[lin];
        *(uint4*)(sm + QLO + off) = Ql4[lin];
        *(uint4*)(sm + KHI + off) = Kh4[lin];
        *(uint4*)(sm + KLO + off) = Kl4[lin];
    }
    __syncthreads();

    const int wm = wid >> 2, wn = wid & 3;
    const int mbase = wm * 64, nbase = wn * 32;
    const int lr = l & 7, sub = l >> 3;

    float acc[4][4][4];
    #pragma unroll
    for (int a = 0; a < 4; a++)
        #pragma unroll
        for (int b = 0; b < 4; b++)
            #pragma unroll
            for (int c = 0; c < 4; c++) acc[a][b][c] = 0.f;

    const int arow_lane = lr + (sub & 1) * 8;
    const uint32_t akc_lane = (uint32_t)((sub >> 1) * 8);
    const uint32_t bkc_lane = (uint32_t)((sub & 1) * 8);

    #pragma unroll
    for (int ks = 0; ks < 4; ks++) {
        uint32_t ah[4][4], al[4][4];
        #pragma unroll
        for (int mt = 0; mt < 4; mt++) {
            int row = mbase + mt * 16 + arow_lane;
            uint32_t off = (uint32_t)(row * RS) * 2 + (akc_lane + ks * 16) * 2;
            ldsm_x4(ah[mt], sb + QHI + off);
            ldsm_x4(al[mt], sb + QLO + off);
        }
        #pragma unroll
        for (int nt = 0; nt < 4; nt++) {
            int rowN = nbase + nt * 8 + lr;
            uint32_t off = (uint32_t)(rowN * RS) * 2 + (bkc_lane + ks * 16) * 2;
            uint32_t bhf[2], blf[2];
            ldsm_x2(bhf, sb + KHI + off);
            ldsm_x2(blf, sb + KLO + off);
            #pragma unroll
            for (int mt = 0; mt < 4; mt++) {
                mma16816(acc[mt][nt], ah[mt], bhf);
                mma16816(acc[mt][nt], ah[mt], blf);
                mma16816(acc[mt][nt], al[mt], bhf);
            }
        }
    }

    const int g = l >> 2, q2 = (l & 3) * 2;
    float* so = scores + (size_t)bh * SEQ * SEQ;
    #pragma unroll
    for (int mt = 0; mt < 4; mt++) {
        #pragma unroll
        for (int nt = 0; nt < 4; nt++) {
            int row = m0 + mbase + mt * 16 + g;
            int col = n0 + nbase + nt * 8 + q2;
            *(float2*)&so[(size_t)row * SEQ + col] = make_float2(acc[mt][nt][0], acc[mt][nt][1]);
            *(float2*)&so[(size_t)(row + 8) * SEQ + col] = make_float2(acc[mt][nt][2], acc[mt][nt][3]);
        }
    }
}

// ---------------- Kernel D: masked softmax + bf16 hi/lo attn scratch --------
__inline__ __device__ float warpMax(float v) {
    #pragma unroll
    for (int o = 16; o > 0; o >>= 1) v = fmaxf(v, __shfl_xor_sync(0xffffffffu, v, o));
    return v;
}
__inline__ __device__ float warpSum(float v) {
    #pragma unroll
    for (int o = 16; o > 0; o >>= 1) v += __shfl_xor_sync(0xffffffffu, v, o);
    return v;
}
__global__ __launch_bounds__(256) void softmax_kernel(float* __restrict__ attn,
                                                      const int* __restrict__ mask) {
    const int q = blockIdx.x, bh = blockIdx.y, tid = threadIdx.x;
    float4* row = (float4*)(attn + ((size_t)bh * SEQ + q) * SEQ);
    const int4* mrow = (const int4*)(mask + (size_t)q * SEQ);
    __shared__ float red[8];

    float4 v0 = row[tid], v1 = row[tid + 256];
    int4 k0 = mrow[tid], k1 = mrow[tid + 256];
    v0.x = (k0.x == 0) ? -1.0e9f : v0.x;  v0.y = (k0.y == 0) ? -1.0e9f : v0.y;
    v0.z = (k0.z == 0) ? -1.0e9f : v0.z;  v0.w = (k0.w == 0) ? -1.0e9f : v0.w;
    v1.x = (k1.x == 0) ? -1.0e9f : v1.x;  v1.y = (k1.y == 0) ? -1.0e9f : v1.y;
    v1.z = (k1.z == 0) ? -1.0e9f : v1.z;  v1.w = (k1.w == 0) ? -1.0e9f : v1.w;

    float m = fmaxf(fmaxf(fmaxf(v0.x, v0.y), fmaxf(v0.z, v0.w)),
                    fmaxf(fmaxf(v1.x, v1.y), fmaxf(v1.z, v1.w)));
    m = warpMax(m);
    if ((tid & 31) == 0) red[tid >> 5] = m;
    __syncthreads();
    if (tid < 32) { float t = (tid < 8) ? red[tid] : -3.0e38f; t = warpMax(t); if (tid == 0) red[0] = t; }
    __syncthreads();
    m = red[0];
    __syncthreads();

    v0.x = __expf(v0.x - m); v0.y = __expf(v0.y - m); v0.z = __expf(v0.z - m); v0.w = __expf(v0.w - m);
    v1.x = __expf(v1.x - m); v1.y = __expf(v1.y - m); v1.z = __expf(v1.z - m); v1.w = __expf(v1.w - m);
    float s = (v0.x + v0.y) + (v0.z + v0.w) + (v1.x + v1.y) + (v1.z + v1.w);
    s = warpSum(s);
    if ((tid & 31) == 0) red[tid >> 5] = s;
    __syncthreads();
    if (tid < 32) { float t = (tid < 8) ? red[tid] : 0.f; t = warpSum(t); if (tid == 0) red[0] = t; }
    __syncthreads();
    const float inv = 1.0f / red[0];
    v0.x *= inv; v0.y *= inv; v0.z *= inv; v0.w *= inv;
    v1.x *= inv; v1.y *= inv; v1.z *= inv; v1.w *= inv;
    row[tid] = v0; row[tid + 256] = v1;

    // bf16 hi/lo copies for the AV GEMM
    uint2* rh = (uint2*)(g_ah + ((size_t)bh * SEQ + q) * SEQ);
    uint2* rl = (uint2*)(g_al + ((size_t)bh * SEQ + q) * SEQ);
    uint32_t h01, h23, l01, l23;
    split4(v0, h01, h23, l01, l23);
    rh[tid] = make_uint2(h01, h23);
    rl[tid] = make_uint2(l01, l23);
    split4(v1, h01, h23, l01, l23);
    rh[tid + 256] = make_uint2(h01, h23);
    rl[tid + 256] = make_uint2(l01, l23);
}

// ---------------- Kernel E: out = attn @ V (HMMA, prefetched bf16) ----------
__global__ __launch_bounds__(256) void attnv_mma(float* __restrict__ out) {
    extern __shared__ char sm[];
    constexpr int AHI = 0, ALO = 18432, BHI = 36864, BLO = 46080;
    const uint32_t sb = smem_u32(sm);
    const int tid = threadIdx.x, wid = tid >> 5, l = tid & 31;
    const int bh = blockIdx.y, m0 = blockIdx.x * 128;

    const int wm = wid >> 1, wn = wid & 1;
    const int mbase = wm * 32, nbase = wn * 32;
    const int lr = l & 7, sub = l >> 3;
    const int arow_lane = lr + (sub & 1) * 8;
    const uint32_t akc_lane = (uint32_t)((sub >> 1) * 8);
    const uint32_t bkc_lane = (uint32_t)((sub & 1) * 8);

    // A tile rows: 2048 bf16 = 256 uint4 per row
    const uint4* Ah4 = (const uint4*)(g_ah + ((size_t)bh * SEQ + m0) * SEQ);
    const uint4* Al4 = (const uint4*)(g_al + ((size_t)bh * SEQ + m0) * SEQ);
    const uint4* Vh4 = (const uint4*)(g_vt_hi + (size_t)bh * DIM * SEQ);
    const uint4* Vl4 = (const uint4*)(g_vt_lo + (size_t)bh * DIM * SEQ);

    // per-thread load coordinates
    const int ar0 = tid >> 3, ac = tid & 7;          // A: rows tid>>3 (+32 per p), col c
    const int bn0 = tid >> 3;                         // B: rows (n) 0..31 for p=0, 32..63 p=1

    float acc[2][4][4];
    #pragma unroll
    for (int a = 0; a < 2; a++)
        #pragma unroll
        for (int b = 0; b < 4; b++)
            #pragma unroll
            for (int c = 0; c < 4; c++) acc[a][b][c] = 0.f;

    uint4 pah[4], pal[4], pbh[2], pbl[2];
    // prefetch chunk 0
    #pragma unroll
    for (int p = 0; p < 4; p++) {
        size_t gi = (size_t)(ar0 + p * 32) * 256 + ac;
        pah[p] = Ah4[gi];
        pal[p] = Al4[gi];
    }
    #pragma unroll
    for (int p = 0; p < 2; p++) {
        size_t gi = (size_t)(bn0 + p * 32) * 256 + ac;
        pbh[p] = Vh4[gi];
        pbl[p] = Vl4[gi];
    }

    for (int kt = 0; kt < SEQ / 64; kt++) {
        // store prefetched chunk to smem
        #pragma unroll
        for (int p = 0; p < 4; p++) {
            int r = ar0 + p * 32;
            uint32_t off = (uint32_t)(r * RS + ac * 8) * 2;
            *(uint4*)(sm + AHI + off) = pah[p];
            *(uint4*)(sm + ALO + off) = pal[p];
        }
        #pragma unroll
        for (int p = 0; p < 2; p++) {
            int n = bn0 + p * 32;
            uint32_t off = (uint32_t)(n * RS + ac * 8) * 2;
            *(uint4*)(sm + BHI + off) = pbh[p];
            *(uint4*)(sm + BLO + off) = pbl[p];
        }
        __syncthreads();

        // prefetch next chunk (loads overlap with MMA below)
        if (kt + 1 < SEQ / 64) {
            int c8 = (kt + 1) * 8 + ac;
            #pragma unroll
            for (int p = 0; p < 4; p++) {
                size_t gi = (size_t)(ar0 + p * 32) * 256 + c8;
                pah[p] = Ah4[gi];
                pal[p] = Al4[gi];
            }
            #pragma unroll
            for (int p = 0; p < 2; p++) {
                size_t gi = (size_t)(bn0 + p * 32) * 256 + c8;
                pbh[p] = Vh4[gi];
                pbl[p] = Vl4[gi];
            }
        }

        #pragma unroll
        for (int ks = 0; ks < 4; ks++) {
            uint32_t ah[2][4], al[2][4];
            #pragma unroll
            for (int mt = 0; mt < 2; mt++) {
                int row = mbase + mt * 16 + arow_lane;
                uint32_t off = (uint32_t)(row * RS) * 2 + (akc_lane + ks * 16) * 2;
                ldsm_x4(ah[mt], sb + AHI + off);
                ldsm_x4(al[mt], sb + ALO + off);
            }
            #pragma unroll
            for (int nt = 0; nt < 4; nt++) {
                int rowN = nbase + nt * 8 + lr;
                uint32_t off = (uint32_t)(rowN * RS) * 2 + (bkc_lane + ks * 16) * 2;
                uint32_t bhf[2], blf[2];
                ldsm_x2(bhf, sb + BHI + off);
                ldsm_x2(blf, sb + BLO + off);
                #pragma unroll
                for (int mt = 0; mt < 2; mt++) {
                    mma16816(acc[mt][nt], ah[mt], bhf);
                    mma16816(acc[mt][nt], ah[mt], blf);
                    mma16816(acc[mt][nt], al[mt], bhf);
                }
            }
        }
        __syncthreads();
    }

    const int g = l >> 2, q2 = (l & 3) * 2;
    float* ob = out + ((size_t)bh * SEQ + m0) * DIM;
    #pragma unroll
    for (int mt = 0; mt < 2; mt++) {
        #pragma unroll
        for (int nt = 0; nt < 4; nt++) {
            int row = mbase + mt * 16 + g;
            int col = nbase + nt * 8 + q2;
            *(float2*)&ob[(size_t)row * DIM + col] = make_float2(acc[mt][nt][0], acc[mt][nt][1]);
            *(float2*)&ob[(size_t)(row + 8) * DIM + col] = make_float2(acc[mt][nt][2], acc[mt][nt][3]);
        }
    }
}

// ---------------- launch ----------------
extern "C" void kernel_launch(void* const* d_in, const int* in_sizes, int n_in,
                              void* d_out, int out_size) {
    const float* Q    = (const float*)d_in[0];
    const float* K    = (const float*)d_in[1];
    const float* V    = (const float*)d_in[2];
    const int*   mask = (const int*)d_in[3];

    float* out  = (float*)d_out;                      // [B,H,S,D]
    float* attn = out + (size_t)NBH * SEQ * DIM;      // [B,H,S,S]

    constexpr int QK_SMEM = 4 * 128 * RS * 2;                    // 73728
    constexpr int AV_SMEM = 2 * 128 * RS * 2 + 2 * 64 * RS * 2;  // 55296
    cudaFuncSetAttribute(qk_mma, cudaFuncAttributeMaxDynamicSharedMemorySize, QK_SMEM);
    cudaFuncSetAttribute(attnv_mma, cudaFuncAttributeMaxDynamicSharedMemorySize, AV_SMEM);

    __nv_bfloat16 *qh, *ql, *kh, *kl;
    cudaGetSymbolAddress((void**)&qh, g_qh);
    cudaGetSymbolAddress((void**)&ql, g_ql);
    cudaGetSymbolAddress((void**)&kh, g_kh);
    cudaGetSymbolAddress((void**)&kl, g_kl);

    const int nsplit = (int)((size_t)NBH * SEQ * DIM / 4 / 256);   // 4096 blocks
    split_prep<<<nsplit, 256>>>(Q, qh, ql, 0.125f);
    split_prep<<<nsplit, 256>>>(K, kh, kl, 1.0f);

    dim3 g0(SEQ / 128, NBH);
    vt_prep<<<g0, 256>>>(V);

    dim3 g1(SEQ / 128, SEQ / 128, NBH);
    qk_mma<<<g1, 256, QK_SMEM>>>(attn);

    dim3 g2(SEQ, NBH);
    softmax_kernel<<<g2, 256>>>(attn, mask);

    dim3 g3(SEQ / 128, NBH);
    attnv_mma<<<g3, 256, AV_SMEM>>>(out);
}

// round 7
// speedup vs baseline: 1.4607x; 1.1246x over previous
#include <cuda_runtime.h>
#include <cuda_bf16.h>
#include <cstdint>

#define SEQ 2048
#define DIM 64
#define NBH 32   // B*H
#define RS 72    // smem row stride in bf16 (144B, conflict-free ldmatrix)

// Scratch (device globals; no allocs allowed)
__device__ __nv_bfloat16 g_qh[(size_t)NBH * SEQ * DIM];
__device__ __nv_bfloat16 g_ql[(size_t)NBH * SEQ * DIM];
__device__ __nv_bfloat16 g_kh[(size_t)NBH * SEQ * DIM];
__device__ __nv_bfloat16 g_kl[(size_t)NBH * SEQ * DIM];
__device__ __nv_bfloat16 g_vt_hi[(size_t)NBH * DIM * SEQ];
__device__ __nv_bfloat16 g_vt_lo[(size_t)NBH * DIM * SEQ];
__device__ __nv_bfloat16 g_ah[(size_t)NBH * SEQ * SEQ];   // unnormalized exp, hi
__device__ __nv_bfloat16 g_al[(size_t)NBH * SEQ * SEQ];   // unnormalized exp, lo
__device__ float    g_inv[(size_t)NBH * SEQ];
__device__ uint32_t g_mbits[(size_t)SEQ * (SEQ / 32)];

// ---------------- helpers ----------------
__device__ __forceinline__ uint32_t smem_u32(const void* p) {
    uint32_t a;
    asm("{ .reg .u64 t; cvta.to.shared.u64 t, %1; cvt.u32.u64 %0, t; }" : "=r"(a) : "l"(p));
    return a;
}
__device__ __forceinline__ void ldsm_x4(uint32_t r[4], uint32_t addr) {
    asm volatile("ldmatrix.sync.aligned.m8n8.x4.shared.b16 {%0,%1,%2,%3}, [%4];"
        : "=r"(r[0]), "=r"(r[1]), "=r"(r[2]), "=r"(r[3]) : "r"(addr));
}
__device__ __forceinline__ void ldsm_x2(uint32_t r[2], uint32_t addr) {
    asm volatile("ldmatrix.sync.aligned.m8n8.x2.shared.b16 {%0,%1}, [%2];"
        : "=r"(r[0]), "=r"(r[1]) : "r"(addr));
}
__device__ __forceinline__ void mma16816(float c[4], const uint32_t a[4], const uint32_t b[2]) {
    asm volatile(
        "mma.sync.aligned.m16n8k16.row.col.f32.bf16.bf16.f32 "
        "{%0,%1,%2,%3}, {%4,%5,%6,%7}, {%8,%9}, {%0,%1,%2,%3};"
        : "+f"(c[0]), "+f"(c[1]), "+f"(c[2]), "+f"(c[3])
        : "r"(a[0]), "r"(a[1]), "r"(a[2]), "r"(a[3]), "r"(b[0]), "r"(b[1]));
}
__device__ __forceinline__ void cp16(uint32_t dst, const void* src) {
    asm volatile("{ .reg .u64 g; cvta.to.global.u64 g, %1; cp.async.cg.shared.global [%0], [g], 16; }"
        :: "r"(dst), "l"(src) : "memory");
}
#define CP_COMMIT asm volatile("cp.async.commit_group;" ::: "memory")
#define CP_WAIT0  asm volatile("cp.async.wait_group 0;" ::: "memory")

__device__ __forceinline__ void split4(float4 v, uint32_t& h01, uint32_t& h23,
                                       uint32_t& l01, uint32_t& l23) {
    __nv_bfloat16 h0 = __float2bfloat16_rn(v.x);
    __nv_bfloat16 h1 = __float2bfloat16_rn(v.y);
    __nv_bfloat16 h2 = __float2bfloat16_rn(v.z);
    __nv_bfloat16 h3 = __float2bfloat16_rn(v.w);
    __nv_bfloat16 q0 = __float2bfloat16_rn(v.x - __bfloat162float(h0));
    __nv_bfloat16 q1 = __float2bfloat16_rn(v.y - __bfloat162float(h1));
    __nv_bfloat16 q2 = __float2bfloat16_rn(v.z - __bfloat162float(h2));
    __nv_bfloat16 q3 = __float2bfloat16_rn(v.w - __bfloat162float(h3));
    h01 = (uint32_t)__bfloat16_as_ushort(h0) | ((uint32_t)__bfloat16_as_ushort(h1) << 16);
    h23 = (uint32_t)__bfloat16_as_ushort(h2) | ((uint32_t)__bfloat16_as_ushort(h3) << 16);
    l01 = (uint32_t)__bfloat16_as_ushort(q0) | ((uint32_t)__bfloat16_as_ushort(q1) << 16);
    l23 = (uint32_t)__bfloat16_as_ushort(q2) | ((uint32_t)__bfloat16_as_ushort(q3) << 16);
}
__device__ __forceinline__ void pack2(float a, float b, uint32_t& h, uint32_t& lo) {
    __nv_bfloat16 h0 = __float2bfloat16_rn(a), h1 = __float2bfloat16_rn(b);
    __nv_bfloat16 l0 = __float2bfloat16_rn(a - __bfloat162float(h0));
    __nv_bfloat16 l1 = __float2bfloat16_rn(b - __bfloat162float(h1));
    h  = (uint32_t)__bfloat16_as_ushort(h0) | ((uint32_t)__bfloat16_as_ushort(h1) << 16);
    lo = (uint32_t)__bfloat16_as_ushort(l0) | ((uint32_t)__bfloat16_as_ushort(l1) << 16);
}
__device__ __forceinline__ float2 pairval(uint32_t h, uint32_t l, float iv) {
    float2 fh = __bfloat1622float2(*(__nv_bfloat162*)&h);
    float2 fl = __bfloat1622float2(*(__nv_bfloat162*)&l);
    return make_float2((fh.x + fl.x) * iv, (fh.y + fl.y) * iv);
}

// ---------------- Kernel A: mask -> bitmask ----------------
__global__ __launch_bounds__(256) void mask_compress(const int* __restrict__ mask) {
    int w = blockIdx.x * 256 + threadIdx.x;
    const int4* m4 = (const int4*)mask + (size_t)w * 8;
    uint32_t b = 0;
    #pragma unroll
    for (int i = 0; i < 8; i++) {
        int4 v = m4[i];
        b |= (uint32_t)(v.x != 0) << (i * 4 + 0);
        b |= (uint32_t)(v.y != 0) << (i * 4 + 1);
        b |= (uint32_t)(v.z != 0) << (i * 4 + 2);
        b |= (uint32_t)(v.w != 0) << (i * 4 + 3);
    }
    g_mbits[w] = b;
}

// ---------------- Kernel B: fp32 -> bf16 hi/lo (scaled) ----------------
__global__ __launch_bounds__(256) void split_prep(const float* __restrict__ X,
                                                  __nv_bfloat16* __restrict__ hi,
                                                  __nv_bfloat16* __restrict__ lo,
                                                  float scale) {
    size_t i = (size_t)blockIdx.x * 256 + threadIdx.x;
    float4 v = ((const float4*)X)[i];
    v.x *= scale; v.y *= scale; v.z *= scale; v.w *= scale;
    uint32_t h01, h23, l01, l23;
    split4(v, h01, h23, l01, l23);
    ((uint2*)hi)[i] = make_uint2(h01, h23);
    ((uint2*)lo)[i] = make_uint2(l01, l23);
}

// ---------------- Kernel C: V -> Vt (bf16 hi/lo, [bh][n][k]) ----------------
__global__ __launch_bounds__(256) void vt_prep(const float* __restrict__ V) {
    __shared__ float tile[128][DIM + 1];
    const int bh = blockIdx.y;
    const int k0 = blockIdx.x * 128;
    const int tid = threadIdx.x;

    const float4* V4 = (const float4*)(V + ((size_t)bh * SEQ + k0) * DIM);
    #pragma unroll
    for (int p = 0; p < 8; p++) {
        int lin = tid + p * 256;
        int r = lin >> 4, j = lin & 15;
        float4 v = V4[lin];
        tile[r][j * 4 + 0] = v.x; tile[r][j * 4 + 1] = v.y;
        tile[r][j * 4 + 2] = v.z; tile[r][j * 4 + 3] = v.w;
    }
    __syncthreads();
    #pragma unroll
    for (int p = 0; p < 32; p++) {
        int lin = tid + p * 256;
        int n = lin >> 7, k = lin & 127;
        float x = tile[k][n];
        __nv_bfloat16 h = __float2bfloat16_rn(x);
        __nv_bfloat16 l = __float2bfloat16_rn(x - __bfloat162float(h));
        size_t o = ((size_t)bh * DIM + n) * SEQ + k0 + k;
        g_vt_hi[o] = h;
        g_vt_lo[o] = l;
    }
}

// ---- K chunk loader for qk strip ----
__device__ __forceinline__ void issue_k(uint32_t dhi, uint32_t dlo,
                                        const uint4* Kh4, const uint4* Kl4,
                                        int kt, int tid) {
    const uint4* kh = Kh4 + (size_t)kt * 128 * 8;
    const uint4* kl = Kl4 + (size_t)kt * 128 * 8;
    #pragma unroll
    for (int p = 0; p < 4; p++) {
        int lin = tid + p * 256;
        int r = lin >> 3, c = lin & 7;
        uint32_t off = (uint32_t)(r * RS + c * 8) * 2;
        cp16(dhi + off, kh + lin);
        cp16(dlo + off, kl + lin);
    }
}

// ---------------- Kernel D: row-strip QK + exp + rowsums --------------------
// Block = 128 rows x full 2048 cols. Writes unnormalized exp (bf16 hi/lo) + g_inv.
__global__ __launch_bounds__(256, 2) void qk_exp_strip() {
    extern __shared__ char sm[];
    __shared__ float spsum[128];
    const uint32_t sb = smem_u32(sm);
    const int tid = threadIdx.x, wid = tid >> 5, l = tid & 31;
    const int m0 = blockIdx.x * 128, bh = blockIdx.y;

    if (tid < 128) spsum[tid] = 0.f;

    constexpr uint32_t QHI = 0, QLO = 18432, KB = 36864, KBSZ = 36864;

    const uint4* Qh4 = (const uint4*)(g_qh + ((size_t)bh * SEQ + m0) * DIM);
    const uint4* Ql4 = (const uint4*)(g_ql + ((size_t)bh * SEQ + m0) * DIM);
    const uint4* Kh4 = (const uint4*)(g_kh + (size_t)bh * SEQ * DIM);
    const uint4* Kl4 = (const uint4*)(g_kl + (size_t)bh * SEQ * DIM);

    // prologue: Q tiles + K chunk 0
    #pragma unroll
    for (int p = 0; p < 4; p++) {
        int lin = tid + p * 256;
        int r = lin >> 3, c = lin & 7;
        uint32_t off = (uint32_t)(r * RS + c * 8) * 2;
        cp16(sb + QHI + off, Qh4 + lin);
        cp16(sb + QLO + off, Ql4 + lin);
    }
    CP_COMMIT;
    issue_k(sb + KB, sb + KB + 18432, Kh4, Kl4, 0, tid);
    CP_COMMIT;
    CP_WAIT0;
    __syncthreads();

    const int wm = wid >> 2, wn = wid & 3;
    const int mbase = wm * 64, nbase = wn * 32;
    const int lr = l & 7, sub = l >> 3;
    const int arow_lane = lr + (sub & 1) * 8;
    const uint32_t akc = (uint32_t)((sub >> 1) * 8);
    const uint32_t bkc = (uint32_t)((sub & 1) * 8);
    const int g = l >> 2, q2 = (l & 3) * 2;

    float rs[4][2] = {};
    __nv_bfloat16* aho = g_ah + (size_t)bh * SEQ * SEQ;
    __nv_bfloat16* alo = g_al + (size_t)bh * SEQ * SEQ;

    for (int kt = 0; kt < 16; kt++) {
        if (kt + 1 < 16) {
            uint32_t b = (uint32_t)((kt + 1) & 1) * KBSZ;
            issue_k(sb + KB + b, sb + KB + b + 18432, Kh4, Kl4, kt + 1, tid);
            CP_COMMIT;
        }
        const uint32_t KHIb = sb + KB + (uint32_t)(kt & 1) * KBSZ;
        const uint32_t KLOb = KHIb + 18432;

        float acc[4][4][4];
        #pragma unroll
        for (int a = 0; a < 4; a++)
            #pragma unroll
            for (int b = 0; b < 4; b++)
                #pragma unroll
                for (int c = 0; c < 4; c++) acc[a][b][c] = 0.f;

        #pragma unroll
        for (int ks = 0; ks < 4; ks++) {
            uint32_t ah[4][4], al[4][4];
            #pragma unroll
            for (int mt = 0; mt < 4; mt++) {
                int row = mbase + mt * 16 + arow_lane;
                uint32_t off = (uint32_t)(row * RS) * 2 + (akc + ks * 16) * 2;
                ldsm_x4(ah[mt], sb + QHI + off);
                ldsm_x4(al[mt], sb + QLO + off);
            }
            #pragma unroll
            for (int nt = 0; nt < 4; nt++) {
                int rowN = nbase + nt * 8 + lr;
                uint32_t off = (uint32_t)(rowN * RS) * 2 + (bkc + ks * 16) * 2;
                uint32_t bhf[2], blf[2];
                ldsm_x2(bhf, KHIb + off);
                ldsm_x2(blf, KLOb + off);
                #pragma unroll
                for (int mt = 0; mt < 4; mt++) {
                    mma16816(acc[mt][nt], ah[mt], bhf);
                    mma16816(acc[mt][nt], ah[mt], blf);
                    mma16816(acc[mt][nt], al[mt], bhf);
                }
            }
        }

        // epilogue: mask + exp + bf16 hi/lo stores + register row sums
        #pragma unroll
        for (int mt = 0; mt < 4; mt++) {
            int rl0 = mbase + mt * 16 + g;
            int row0 = m0 + rl0;
            uint32_t w0 = g_mbits[(size_t)row0 * 64 + kt * 4 + wn];
            uint32_t w1 = g_mbits[(size_t)(row0 + 8) * 64 + kt * 4 + wn];
            #pragma unroll
            for (int nt = 0; nt < 4; nt++) {
                int cb = nt * 8 + q2;
                float e0 = ((w0 >> cb) & 1)       ? __expf(acc[mt][nt][0]) : 0.f;
                float e1 = ((w0 >> (cb + 1)) & 1) ? __expf(acc[mt][nt][1]) : 0.f;
                float e2 = ((w1 >> cb) & 1)       ? __expf(acc[mt][nt][2]) : 0.f;
                float e3 = ((w1 >> (cb + 1)) & 1) ? __expf(acc[mt][nt][3]) : 0.f;
                rs[mt][0] += e0 + e1;
                rs[mt][1] += e2 + e3;
                size_t o0 = (size_t)row0 * SEQ + kt * 128 + nbase + cb;
                size_t o1 = o0 + (size_t)8 * SEQ;
                uint32_t h01, l01, h23, l23;
                pack2(e0, e1, h01, l01);
                pack2(e2, e3, h23, l23);
                *(uint32_t*)&aho[o0] = h01;
                *(uint32_t*)&alo[o0] = l01;
                *(uint32_t*)&aho[o1] = h23;
                *(uint32_t*)&alo[o1] = l23;
            }
        }

        if (kt + 1 < 16) CP_WAIT0;
        __syncthreads();
    }

    // strip row sums -> g_inv
    #pragma unroll
    for (int mt = 0; mt < 4; mt++) {
        float s0 = rs[mt][0], s1 = rs[mt][1];
        s0 += __shfl_xor_sync(0xffffffffu, s0, 1);
        s0 += __shfl_xor_sync(0xffffffffu, s0, 2);
        s1 += __shfl_xor_sync(0xffffffffu, s1, 1);
        s1 += __shfl_xor_sync(0xffffffffu, s1, 2);
        if ((l & 3) == 0) {
            atomicAdd(&spsum[mbase + mt * 16 + g], s0);
            atomicAdd(&spsum[mbase + mt * 16 + g + 8], s1);
        }
    }
    __syncthreads();
    if (tid < 128)
        g_inv[(size_t)bh * SEQ + m0 + tid] = 1.0f / spsum[tid];
}

// ---------------- Kernel E: out = p@V * inv, attn = p * inv -----------------
__global__ __launch_bounds__(256, 2) void attnv_fused(float* __restrict__ attn,
                                                      float* __restrict__ out) {
    extern __shared__ char sm[];
    __shared__ float sinv[128];
    const uint32_t sb = smem_u32(sm);
    const int tid = threadIdx.x, wid = tid >> 5, l = tid & 31;
    const int m0 = blockIdx.x * 128, bh = blockIdx.y;

    if (tid < 128) sinv[tid] = g_inv[(size_t)bh * SEQ + m0 + tid];

    constexpr uint32_t BSZ = 55296, AHI = 0, ALO = 18432, BHI = 36864, BLO = 46080;

    const uint4* Ah4 = (const uint4*)(g_ah + ((size_t)bh * SEQ + m0) * SEQ);
    const uint4* Al4 = (const uint4*)(g_al + ((size_t)bh * SEQ + m0) * SEQ);
    const uint4* Vh4 = (const uint4*)(g_vt_hi + (size_t)bh * DIM * SEQ);
    const uint4* Vl4 = (const uint4*)(g_vt_lo + (size_t)bh * DIM * SEQ);

    const int ar0 = tid >> 3, ac = tid & 7;

    // chunk issue helper (inlined twice)
    auto issue_chunk = [&](int kt, uint32_t base) {
        #pragma unroll
        for (int p = 0; p < 4; p++) {
            int r = ar0 + p * 32;
            uint32_t off = (uint32_t)(r * RS + ac * 8) * 2;
            size_t gi = (size_t)r * 256 + kt * 8 + ac;
            cp16(sb + base + AHI + off, Ah4 + gi);
            cp16(sb + base + ALO + off, Al4 + gi);
        }
        #pragma unroll
        for (int p = 0; p < 2; p++) {
            int n = ar0 + p * 32;
            uint32_t off = (uint32_t)(n * RS + ac * 8) * 2;
            size_t gi = (size_t)n * 256 + kt * 8 + ac;
            cp16(sb + base + BHI + off, Vh4 + gi);
            cp16(sb + base + BLO + off, Vl4 + gi);
        }
    };

    issue_chunk(0, 0);
    CP_COMMIT;
    CP_WAIT0;
    __syncthreads();

    const int wm = wid >> 1, wn = wid & 1;
    const int mbase = wm * 32, nbase = wn * 32;
    const int lr = l & 7, sub = l >> 3;
    const int arow_lane = lr + (sub & 1) * 8;
    const uint32_t akc = (uint32_t)((sub >> 1) * 8);
    const uint32_t bkc = (uint32_t)((sub & 1) * 8);

    float acc[2][4][4];
    #pragma unroll
    for (int a = 0; a < 2; a++)
        #pragma unroll
        for (int b = 0; b < 4; b++)
            #pragma unroll
            for (int c = 0; c < 4; c++) acc[a][b][c] = 0.f;

    float* arow = attn + ((size_t)bh * SEQ + m0) * SEQ;

    for (int kt = 0; kt < 32; kt++) {
        if (kt + 1 < 32) {
            issue_chunk(kt + 1, (uint32_t)((kt + 1) & 1) * BSZ);
            CP_COMMIT;
        }
        const uint32_t base = (uint32_t)(kt & 1) * BSZ;

        // stream normalized fp32 attn from this chunk's smem copy
        #pragma unroll
        for (int p = 0; p < 4; p++) {
            int r = ar0 + p * 32;
            uint32_t off = (uint32_t)(r * RS + ac * 8) * 2;
            uint4 hh = *(const uint4*)(sm + base + AHI + off);
            uint4 ll = *(const uint4*)(sm + base + ALO + off);
            float iv = sinv[r];
            float2 a0 = pairval(hh.x, ll.x, iv);
            float2 a1 = pairval(hh.y, ll.y, iv);
            float2 a2 = pairval(hh.z, ll.z, iv);
            float2 a3 = pairval(hh.w, ll.w, iv);
            size_t o = (size_t)r * SEQ + kt * 64 + ac * 8;
            *(float4*)&arow[o]     = make_float4(a0.x, a0.y, a1.x, a1.y);
            *(float4*)&arow[o + 4] = make_float4(a2.x, a2.y, a3.x, a3.y);
        }

        #pragma unroll
        for (int ks = 0; ks < 4; ks++) {
            uint32_t ah[2][4], al[2][4];
            #pragma unroll
            for (int mt = 0; mt < 2; mt++) {
                int row = mbase + mt * 16 + arow_lane;
                uint32_t off = (uint32_t)(row * RS) * 2 + (akc + ks * 16) * 2;
                ldsm_x4(ah[mt], sb + base + AHI + off);
                ldsm_x4(al[mt], sb + base + ALO + off);
            }
            #pragma unroll
            for (int nt = 0; nt < 4; nt++) {
                int rowN = nbase + nt * 8 + lr;
                uint32_t off = (uint32_t)(rowN * RS) * 2 + (bkc + ks * 16) * 2;
                uint32_t bhf[2], blf[2];
                ldsm_x2(bhf, sb + base + BHI + off);
                ldsm_x2(blf, sb + base + BLO + off);
                #pragma unroll
                for (int mt = 0; mt < 2; mt++) {
                    mma16816(acc[mt][nt], ah[mt], bhf);
                    mma16816(acc[mt][nt], ah[mt], blf);
                    mma16816(acc[mt][nt], al[mt], bhf);
                }
            }
        }

        if (kt + 1 < 32) CP_WAIT0;
        __syncthreads();
    }

    const int g = l >> 2, q2 = (l & 3) * 2;
    float* ob = out + ((size_t)bh * SEQ + m0) * DIM;
    #pragma unroll
    for (int mt = 0; mt < 2; mt++) {
        int rl = mbase + mt * 16 + g;
        float iv0 = sinv[rl], iv1 = sinv[rl + 8];
        #pragma unroll
        for (int nt = 0; nt < 4; nt++) {
            int col = nbase + nt * 8 + q2;
            *(float2*)&ob[(size_t)rl * DIM + col] =
                make_float2(acc[mt][nt][0] * iv0, acc[mt][nt][1] * iv0);
            *(float2*)&ob[(size_t)(rl + 8) * DIM + col] =
                make_float2(acc[mt][nt][2] * iv1, acc[mt][nt][3] * iv1);
        }
    }
}

// ---------------- launch ----------------
extern "C" void kernel_launch(void* const* d_in, const int* in_sizes, int n_in,
                              void* d_out, int out_size) {
    const float* Q    = (const float*)d_in[0];
    const float* K    = (const float*)d_in[1];
    const float* V    = (const float*)d_in[2];
    const int*   mask = (const int*)d_in[3];

    float* out  = (float*)d_out;                      // [B,H,S,D]
    float* attn = out + (size_t)NBH * SEQ * DIM;      // [B,H,S,S]

    constexpr int STRIP_SMEM = 110592;
    cudaFuncSetAttribute(qk_exp_strip, cudaFuncAttributeMaxDynamicSharedMemorySize, STRIP_SMEM);
    cudaFuncSetAttribute(attnv_fused, cudaFuncAttributeMaxDynamicSharedMemorySize, STRIP_SMEM);

    __nv_bfloat16 *qh, *ql, *kh, *kl;
    cudaGetSymbolAddress((void**)&qh, g_qh);
    cudaGetSymbolAddress((void**)&ql, g_ql);
    cudaGetSymbolAddress((void**)&kh, g_kh);
    cudaGetSymbolAddress((void**)&kl, g_kl);

    mask_compress<<<SEQ * (SEQ / 32) / 256, 256>>>(mask);

    const int nsplit = (int)((size_t)NBH * SEQ * DIM / 4 / 256);
    split_prep<<<nsplit, 256>>>(Q, qh, ql, 0.125f);
    split_prep<<<nsplit, 256>>>(K, kh, kl, 1.0f);

    dim3 g0(SEQ / 128, NBH);
    vt_prep<<<g0, 256>>>(V);

    dim3 g1(SEQ / 128, NBH);
    qk_exp_strip<<<g1, 256, STRIP_SMEM>>>();

    dim3 g2(SEQ / 128, NBH);
    attnv_fused<<<g2, 256, STRIP_SMEM>>>(attn, out);
}